// round 7
// baseline (speedup 1.0000x reference)
#include <cuda_runtime.h>
#include <cstdint>

// OR-tree reduction over rows of a (ROWS, 1024) float32 0/1 matrix.
// Reference pairwise-sum >= 0.5 tree == any(x >= 0.5) over the row.
//
// Empirical law from R2-R6: 65536 scattered 128B-line fetches ~ 5.9us on
// this chip regardless of load count / MLP / occupancy; only the de-aliased
// probe offset (sweeping addr bits 7-11 across rows) helped (~5%). This
// round trims the remaining controllable terms: half the CTAs (shorter
// launch ramp), 16 rows per warp with both probe loads issued back-to-back
// (one latency exposure), lean address math.
//
// Layout: warp handles rows [w*16, w*16+16). Lane L -> group g=L>>2 (4 lanes
// per row), float4 index L&3 within the probed 128B line. Iteration i in
// {0,1} covers rows w*16 + i*8 + g. Probe line offset within the row =
// (row & 31)*128 bytes (de-alias). Per-row unresolved prob 2^-16 ->
// expected ~1 rescue group in the whole grid; rescue = warp-uniform batched
// full rescan (correct for any input). rows % 16 == 0.

static constexpr int COLS = 1024;
static constexpr int F4_PER_ROW = COLS / 4; // 256
static constexpr unsigned FULL = 0xffffffffu;

__device__ __forceinline__ bool any_ge_half(const float4 v) {
    return (v.x >= 0.5f) | (v.y >= 0.5f) | (v.z >= 0.5f) | (v.w >= 0.5f);
}

// Warp-uniform rescue: rescan 'row' (4 lanes: f4i = lane&3), return group OR.
__device__ __forceinline__ bool rescue_row(
    const float4* __restrict__ rp, int f4i, unsigned group_mask, int lane)
{
    bool done = false;
    #pragma unroll 1
    for (int base = 0; base < F4_PER_ROW; base += 32) {
        bool f = false;
        #pragma unroll
        for (int j = 0; j < 8; ++j) f |= any_ge_half(rp[base + f4i + 4 * j]);
        const unsigned b = __ballot_sync(FULL, f);
        if (b & group_mask) { done = true; break; }
    }
    return done;
}

__global__ void __launch_bounds__(256) vec_or_tree_kernel(
    const float4* __restrict__ x,
    float* __restrict__ out,
    int rows)
{
    const int warp = (blockIdx.x * blockDim.x + threadIdx.x) >> 5;
    const int lane = threadIdx.x & 31;
    const int rbase = warp * 16;
    if (rbase >= rows) return;

    const int g    = lane >> 2;     // 0..7
    const int f4i  = lane & 3;      // 0..3

    const int row0 = rbase + g;
    const int row1 = row0 + 8;

    const float4* __restrict__ rp0 = x + (size_t)row0 * F4_PER_ROW;
    const float4* __restrict__ rp1 = x + (size_t)row1 * F4_PER_ROW;

    // Two independent probe loads, issued back-to-back (one DRAM exposure).
    // De-aliased line: float4 index (row & 31) * 8.
    const float4 v0 = rp0[((row0 & 31) << 3) + f4i];
    const float4 v1 = rp1[((row1 & 31) << 3) + f4i];

    const unsigned bal0 = __ballot_sync(FULL, any_ge_half(v0));
    const unsigned bal1 = __ballot_sync(FULL, any_ge_half(v1));

    const unsigned gmask = 0xFu << (lane & 28);
    bool done0 = (bal0 & gmask) != 0;
    bool done1 = (bal1 & gmask) != 0;

    // Rescue (expected ~1 group grid-wide): warp-uniform full rescans.
    if (__any_sync(FULL, !done0)) {
        const bool r = rescue_row(rp0, f4i, gmask, lane);
        done0 |= r;
    }
    if (__any_sync(FULL, !done1)) {
        const bool r = rescue_row(rp1, f4i, gmask, lane);
        done1 |= r;
    }

    // Lanes 0,4,...,28 store; 8 consecutive floats per iteration (32B).
    if (f4i == 0) {
        out[row0] = done0 ? 1.0f : 0.0f;
        out[row1] = done1 ? 1.0f : 0.0f;
    }
}

extern "C" void kernel_launch(void* const* d_in, const int* in_sizes, int n_in,
                              void* d_out, int out_size)
{
    const float4* x = (const float4*)d_in[0];
    float* out = (float*)d_out;
    const int rows = in_sizes[0] / COLS;   // 65536 (multiple of 16)

    const int threads = 256;                          // 8 warps/block
    const int rows_per_block = (threads / 32) * 16;   // 128
    const int blocks = (rows + rows_per_block - 1) / rows_per_block;  // 512
    vec_or_tree_kernel<<<blocks, threads>>>(x, out, rows);
}